// round 1
// baseline (speedup 1.0000x reference)
#include <cuda_runtime.h>
#include <cuda_bf16.h>
#include <cstdint>

// Problem constants
#define B_   16
#define C_   128
#define H_   128
#define W_   128
#define OUT_ 256
#define HW_  (H_ * W_)          // 16384
#define PLANE (HW_)

// Scratch for depthwise output y: 16*128*128*128 floats = 128 MiB
__device__ float g_y[(size_t)B_ * C_ * HW_];

// ---------------------------------------------------------------------------
// Kernel 1: separable depthwise 3x3 conv (pad 1, stride 1)
// One CTA per (b,c) plane. 128 threads, one per column w.
// Row conv via smem row buffer, column conv via rolling registers.
// ---------------------------------------------------------------------------
__global__ __launch_bounds__(128) void dw_kernel(
    const float* __restrict__ x,
    const float* __restrict__ colk,
    const float* __restrict__ rowk)
{
    const int plane = blockIdx.x;          // b*C + c
    const int c = plane & (C_ - 1);
    const float* xp = x + (size_t)plane * PLANE;
    float* yp = g_y + (size_t)plane * PLANE;

    const float r0 = rowk[c * 3 + 0], r1 = rowk[c * 3 + 1], r2 = rowk[c * 3 + 2];
    const float c0 = colk[c * 3 + 0], c1 = colk[c * 3 + 1], c2 = colk[c * 3 + 2];

    __shared__ float xbuf[W_ + 2];
    const int w = threadIdx.x;

    // row-convolution of row h (cross-correlation, pad 1)
    auto rowconv = [&](int h) -> float {
        __syncthreads();                 // WAR: previous readers done
        xbuf[w + 1] = xp[h * W_ + w];
        if (w == 0) { xbuf[0] = 0.f; xbuf[W_ + 1] = 0.f; }
        __syncthreads();
        return r0 * xbuf[w] + r1 * xbuf[w + 1] + r2 * xbuf[w + 2];
    };

    float t_prev = 0.f;
    float t_cur = rowconv(0);
    #pragma unroll 1
    for (int h = 0; h < H_; ++h) {
        float t_next = (h < H_ - 1) ? rowconv(h + 1) : 0.f;
        yp[h * W_ + w] = c0 * t_prev + c1 * t_cur + c2 * t_next;
        t_prev = t_cur;
        t_cur = t_next;
    }
}

// ---------------------------------------------------------------------------
// Kernel 2: pointwise 1x1 conv as TF32 tensor-core GEMM
//   out[b, o, p] = sum_c W[o, c] * y[b, c, p]
// CTA tile: M=128 (o), N=128 (p), K chunked by 32. 8 warps (4x2), warp 32x64.
// ---------------------------------------------------------------------------
__device__ __forceinline__ uint32_t f2tf32(float f) {
    uint32_t u;
    asm("cvt.rna.tf32.f32 %0, %1;" : "=r"(u) : "f"(f));
    return u;
}

__device__ __forceinline__ void mma_tf32(float* d, const uint32_t* a, const uint32_t* b) {
    asm volatile(
        "mma.sync.aligned.m16n8k8.row.col.f32.tf32.tf32.f32 "
        "{%0,%1,%2,%3}, {%4,%5,%6,%7}, {%8,%9}, {%0,%1,%2,%3};"
        : "+f"(d[0]), "+f"(d[1]), "+f"(d[2]), "+f"(d[3])
        : "r"(a[0]), "r"(a[1]), "r"(a[2]), "r"(a[3]), "r"(b[0]), "r"(b[1]));
}

#define WS_STRIDE 36   // bank = (4m + k) & 31 -> conflict-free frag loads
#define YS_STRIDE 136  // bank = (8k + p) & 31 -> conflict-free frag loads

__global__ __launch_bounds__(256) void pw_kernel(
    const float* __restrict__ Wg,   // (OUT, C) row-major
    float* __restrict__ out)        // (B, OUT, H, W)
{
    __shared__ uint32_t Ws[128][WS_STRIDE];  // [m][k], tf32 bits
    __shared__ uint32_t Ys[32][YS_STRIDE];   // [k][p], tf32 bits

    const int b     = blockIdx.z;
    const int mBase = blockIdx.y * 128;      // output-channel tile base
    const int pBase = blockIdx.x * 128;      // pixel tile base

    const float* yb = g_y + (size_t)b * C_ * HW_ + pBase;
    float* ob = out + (size_t)b * OUT_ * HW_ + (size_t)mBase * HW_ + pBase;

    const int tid  = threadIdx.x;
    const int lane = tid & 31;
    const int warp = tid >> 5;
    const int wm   = warp >> 1;   // 0..3
    const int wn   = warp & 1;    // 0..1

    float acc[2][8][4] = {};

    for (int kb = 0; kb < C_; kb += 32) {
        // --- stage W chunk [128 m][32 k] ---
        #pragma unroll
        for (int i = 0; i < 4; ++i) {
            int idx = tid + i * 256;            // 0..1023
            int row = idx >> 3;                  // m
            int q   = idx & 7;                   // k/4
            float4 v = *(const float4*)(Wg + (size_t)(mBase + row) * C_ + kb + q * 4);
            uint4 t;
            t.x = f2tf32(v.x); t.y = f2tf32(v.y); t.z = f2tf32(v.z); t.w = f2tf32(v.w);
            *(uint4*)&Ws[row][q * 4] = t;
        }
        // --- stage Y chunk [32 k][128 p] ---
        #pragma unroll
        for (int i = 0; i < 4; ++i) {
            int idx = tid + i * 256;            // 0..1023
            int row = idx >> 5;                  // k
            int q   = idx & 31;                  // p/4
            float4 v = *(const float4*)(yb + (size_t)(kb + row) * HW_ + q * 4);
            uint4 t;
            t.x = f2tf32(v.x); t.y = f2tf32(v.y); t.z = f2tf32(v.z); t.w = f2tf32(v.w);
            *(uint4*)&Ys[row][q * 4] = t;
        }
        __syncthreads();

        #pragma unroll
        for (int ks = 0; ks < 4; ++ks) {
            const int k0 = ks * 8;
            uint32_t a[2][4];
            uint32_t bf[8][2];
            #pragma unroll
            for (int mt = 0; mt < 2; ++mt) {
                int m0 = wm * 32 + mt * 16;
                a[mt][0] = Ws[m0 +     (lane >> 2)][k0 +     (lane & 3)];
                a[mt][1] = Ws[m0 + 8 + (lane >> 2)][k0 +     (lane & 3)];
                a[mt][2] = Ws[m0 +     (lane >> 2)][k0 + 4 + (lane & 3)];
                a[mt][3] = Ws[m0 + 8 + (lane >> 2)][k0 + 4 + (lane & 3)];
            }
            #pragma unroll
            for (int nt = 0; nt < 8; ++nt) {
                int n0 = wn * 64 + nt * 8;
                bf[nt][0] = Ys[k0 +     (lane & 3)][n0 + (lane >> 2)];
                bf[nt][1] = Ys[k0 + 4 + (lane & 3)][n0 + (lane >> 2)];
            }
            #pragma unroll
            for (int mt = 0; mt < 2; ++mt)
                #pragma unroll
                for (int nt = 0; nt < 8; ++nt)
                    mma_tf32(acc[mt][nt], a[mt], bf[nt]);
        }
        __syncthreads();
    }

    // epilogue: each warp writes its 32x64 tile
    #pragma unroll
    for (int mt = 0; mt < 2; ++mt) {
        int o0 = wm * 32 + mt * 16 + (lane >> 2);
        #pragma unroll
        for (int nt = 0; nt < 8; ++nt) {
            int p = wn * 64 + nt * 8 + (lane & 3) * 2;
            *(float2*)(ob + (size_t)o0 * HW_ + p) =
                make_float2(acc[mt][nt][0], acc[mt][nt][1]);
            *(float2*)(ob + (size_t)(o0 + 8) * HW_ + p) =
                make_float2(acc[mt][nt][2], acc[mt][nt][3]);
        }
    }
}

// ---------------------------------------------------------------------------
extern "C" void kernel_launch(void* const* d_in, const int* in_sizes, int n_in,
                              void* d_out, int out_size)
{
    (void)in_sizes; (void)n_in; (void)out_size;
    const float* x    = (const float*)d_in[0];
    const float* colk = (const float*)d_in[1];
    const float* rowk = (const float*)d_in[2];
    const float* pw   = (const float*)d_in[3];
    float* out = (float*)d_out;

    dw_kernel<<<B_ * C_, 128>>>(x, colk, rowk);
    pw_kernel<<<dim3(HW_ / 128, OUT_ / 128, B_), 256>>>(pw, out);
}

// round 2
// speedup vs baseline: 1.2143x; 1.2143x over previous
#include <cuda_runtime.h>
#include <cuda_bf16.h>
#include <cstdint>

// Problem constants
#define B_   16
#define C_   128
#define H_   128
#define W_   128
#define OUT_ 256
#define HW_  (H_ * W_)          // 16384

__device__ __forceinline__ uint32_t f2tf32(float f) {
    uint32_t u;
    asm("cvt.rna.tf32.f32 %0, %1;" : "=r"(u) : "f"(f));
    return u;
}

__device__ __forceinline__ void mma_tf32(float* d, const uint32_t* a, const uint32_t* b) {
    asm volatile(
        "mma.sync.aligned.m16n8k8.row.col.f32.tf32.tf32.f32 "
        "{%0,%1,%2,%3}, {%4,%5,%6,%7}, {%8,%9}, {%0,%1,%2,%3};"
        : "+f"(d[0]), "+f"(d[1]), "+f"(d[2]), "+f"(d[3])
        : "r"(a[0]), "r"(a[1]), "r"(a[2]), "r"(a[3]), "r"(b[0]), "r"(b[1]));
}

#define WS_STRIDE 36   // bank = (4m + k) & 31 -> conflict-free A-frag loads
#define YS_STRIDE 136  // bank = (8k + p) & 31 -> conflict-free B-frag loads

// ---------------------------------------------------------------------------
// Fused kernel: one CTA per (b, h) output row.
//   Phase 1: depthwise-separable 3x3 for all 128 channels of row h -> smem (tf32)
//   Phase 2: GEMM  out[b, 0:256, h, :] = W(256x128) @ y(128x128)
// 512 threads = 16 warps, warp grid 4x4, warp tile 64(M) x 32(N).
// ---------------------------------------------------------------------------
__global__ __launch_bounds__(512, 1) void fused_kernel(
    const float* __restrict__ x,
    const float* __restrict__ colk,
    const float* __restrict__ rowk,
    const float* __restrict__ Wg,
    float* __restrict__ out)
{
    __shared__ uint32_t Ys[C_][YS_STRIDE];   // depthwise result [k=c][p=w], tf32 bits
    __shared__ uint32_t Ws[OUT_][WS_STRIDE]; // W chunk [m=o][k within chunk], tf32 bits

    const int h = blockIdx.x;
    const int b = blockIdx.y;

    const int tid  = threadIdx.x;
    const int lane = tid & 31;
    const int warp = tid >> 5;

    // ---------------- Phase 1: depthwise into Ys ----------------
    {
        const unsigned FULL = 0xFFFFFFFFu;
        #pragma unroll
        for (int i = 0; i < 8; ++i) {
            const int c = warp * 8 + i;
            const float r0 = rowk[c * 3 + 0], r1 = rowk[c * 3 + 1], r2 = rowk[c * 3 + 2];
            const float ck[3] = { colk[c * 3 + 0], colk[c * 3 + 1], colk[c * 3 + 2] };
            const float* xc = x + ((size_t)(b * C_ + c) * H_) * W_;

            float y0 = 0.f, y1 = 0.f, y2 = 0.f, y3 = 0.f;
            #pragma unroll
            for (int dr = 0; dr < 3; ++dr) {
                const int row = h - 1 + dr;
                float4 v = make_float4(0.f, 0.f, 0.f, 0.f);
                if (row >= 0 && row < H_)
                    v = *(const float4*)(xc + (size_t)row * W_ + lane * 4);
                float left  = __shfl_up_sync(FULL, v.w, 1);
                float right = __shfl_down_sync(FULL, v.x, 1);
                if (lane == 0)  left = 0.f;
                if (lane == 31) right = 0.f;
                const float kc = ck[dr];
                y0 += kc * (r0 * left + r1 * v.x + r2 * v.y);
                y1 += kc * (r0 * v.x  + r1 * v.y + r2 * v.z);
                y2 += kc * (r0 * v.y  + r1 * v.z + r2 * v.w);
                y3 += kc * (r0 * v.z  + r1 * v.w + r2 * right);
            }

            uint4 ty;
            ty.x = f2tf32(y0); ty.y = f2tf32(y1);
            ty.z = f2tf32(y2); ty.w = f2tf32(y3);
            *(uint4*)&Ys[c][lane * 4] = ty;
        }
    }
    __syncthreads();

    // ---------------- Phase 2: GEMM ----------------
    const int wm = warp >> 2;     // 0..3 -> M offset wm*64
    const int wn = warp & 3;      // 0..3 -> N offset wn*32

    float acc[4][4][4] = {};      // [mt][nt][frag]

    float* ob = out + ((size_t)b * OUT_) * HW_ + (size_t)h * W_;

    for (int kb = 0; kb < C_; kb += 32) {
        // stage W chunk [256 m][32 k] (L2-resident, same for all CTAs)
        #pragma unroll
        for (int i = 0; i < 4; ++i) {
            int idx = tid + i * 512;          // float4 index, 0..2047
            int row = idx >> 3;               // m: 0..255
            int q   = idx & 7;                // k/4
            float4 v = *(const float4*)(Wg + (size_t)row * C_ + kb + q * 4);
            uint4 t;
            t.x = f2tf32(v.x); t.y = f2tf32(v.y); t.z = f2tf32(v.z); t.w = f2tf32(v.w);
            *(uint4*)&Ws[row][q * 4] = t;
        }
        __syncthreads();

        #pragma unroll
        for (int ks = 0; ks < 4; ++ks) {
            const int k0 = ks * 8;
            const int kg = kb + k0;           // global k for Ys
            uint32_t a[4][4];
            uint32_t bf[4][2];
            #pragma unroll
            for (int mt = 0; mt < 4; ++mt) {
                int m0 = wm * 64 + mt * 16;
                a[mt][0] = Ws[m0 +     (lane >> 2)][k0 +     (lane & 3)];
                a[mt][1] = Ws[m0 + 8 + (lane >> 2)][k0 +     (lane & 3)];
                a[mt][2] = Ws[m0 +     (lane >> 2)][k0 + 4 + (lane & 3)];
                a[mt][3] = Ws[m0 + 8 + (lane >> 2)][k0 + 4 + (lane & 3)];
            }
            #pragma unroll
            for (int nt = 0; nt < 4; ++nt) {
                int n0 = wn * 32 + nt * 8;
                bf[nt][0] = Ys[kg +     (lane & 3)][n0 + (lane >> 2)];
                bf[nt][1] = Ys[kg + 4 + (lane & 3)][n0 + (lane >> 2)];
            }
            #pragma unroll
            for (int mt = 0; mt < 4; ++mt)
                #pragma unroll
                for (int nt = 0; nt < 4; ++nt)
                    mma_tf32(acc[mt][nt], a[mt], bf[nt]);
        }
        __syncthreads();
    }

    // ---------------- Epilogue ----------------
    #pragma unroll
    for (int mt = 0; mt < 4; ++mt) {
        int o0 = wm * 64 + mt * 16 + (lane >> 2);
        #pragma unroll
        for (int nt = 0; nt < 4; ++nt) {
            int p = wn * 32 + nt * 8 + (lane & 3) * 2;
            *(float2*)(ob + (size_t)o0 * HW_ + p) =
                make_float2(acc[mt][nt][0], acc[mt][nt][1]);
            *(float2*)(ob + (size_t)(o0 + 8) * HW_ + p) =
                make_float2(acc[mt][nt][2], acc[mt][nt][3]);
        }
    }
}

// ---------------------------------------------------------------------------
extern "C" void kernel_launch(void* const* d_in, const int* in_sizes, int n_in,
                              void* d_out, int out_size)
{
    (void)in_sizes; (void)n_in; (void)out_size;
    const float* x    = (const float*)d_in[0];
    const float* colk = (const float*)d_in[1];
    const float* rowk = (const float*)d_in[2];
    const float* pw   = (const float*)d_in[3];
    float* out = (float*)d_out;

    fused_kernel<<<dim3(H_, B_), 512>>>(x, colk, rowk, pw, out);
}

// round 4
// speedup vs baseline: 1.2643x; 1.0412x over previous
#include <cuda_runtime.h>
#include <cstdint>

// Problem constants
#define B_   16
#define C_   128
#define H_   128
#define W_   128
#define OUT_ 256
#define HW_  (H_ * W_)

// Pre-packed W in A-fragment order: [kstep 16][mtile 16][lane 32][word 4], tf32 bits.
//   word w, lane l -> W[mtile*16 + (w&1)*8 + (l>>2)][kstep*8 + (w>>1)*4 + (l&3)]
__device__ uint32_t g_AF[16 * 16 * 32 * 4];   // 128 KB

#define SMEM_AF  0            // 131072 bytes
#define SMEM_Y   131072       // Ys [128 k][136 stride] f32 = 69632 bytes
#define YS_STRIDE 136
#define SMEM_TOT (SMEM_Y + C_ * YS_STRIDE * 4)   // 200704

__device__ __forceinline__ uint32_t f2tf32(float f) {
    uint32_t u;
    asm("cvt.rna.tf32.f32 %0, %1;" : "=r"(u) : "f"(f));
    return u;
}

__device__ __forceinline__ uint32_t s2u(const void* p) {
    uint32_t a;
    asm("{ .reg .u64 t; cvta.to.shared.u64 t, %1; cvt.u32.u64 %0, t; }" : "=r"(a) : "l"(p));
    return a;
}

__device__ __forceinline__ void mma_tf32(float* d, const uint32_t* a, const uint32_t* b) {
    asm volatile(
        "mma.sync.aligned.m16n8k8.row.col.f32.tf32.tf32.f32 "
        "{%0,%1,%2,%3}, {%4,%5,%6,%7}, {%8,%9}, {%0,%1,%2,%3};"
        : "+f"(d[0]), "+f"(d[1]), "+f"(d[2]), "+f"(d[3])
        : "r"(a[0]), "r"(a[1]), "r"(a[2]), "r"(a[3]), "r"(b[0]), "r"(b[1]));
}

// ---------------------------------------------------------------------------
// Prep kernel: pack W (OUT x C, f32) into fragment-ordered tf32 image g_AF.
// ---------------------------------------------------------------------------
__global__ __launch_bounds__(512) void prep_kernel(const float* __restrict__ Wg) {
    const int idx   = blockIdx.x * 512 + threadIdx.x;   // 0..32767
    const int wrd   = idx & 3;
    const int lane  = (idx >> 2) & 31;
    const int mtile = (idx >> 7) & 15;
    const int kstep = idx >> 11;
    const int m = mtile * 16 + ((wrd & 1) << 3) + (lane >> 2);
    const int k = kstep * 8 + ((wrd >> 1) << 2) + (lane & 3);
    g_AF[idx] = f2tf32(Wg[m * C_ + k]);
}

// ---------------------------------------------------------------------------
// Fused kernel: one CTA per (b, h) output row. 512 threads = 16 warps (4x4).
//   Phase 0: cp.async bulk copy of g_AF (128 KB) into smem (overlaps phase 1)
//   Phase 1: depthwise-separable 3x3, all 128 channels of row h -> Ys (tf32)
//   Phase 2: GEMM out[b,:,h,:] = W(256x128) @ y(128x128), single mma stream
// ---------------------------------------------------------------------------
__global__ __launch_bounds__(512, 1) void fused_kernel(
    const float* __restrict__ x,
    const float* __restrict__ colk,
    const float* __restrict__ rowk,
    float* __restrict__ out)
{
    extern __shared__ char smem[];
    const uint32_t sb = s2u(smem);

    const int tid  = threadIdx.x;
    const int lane = tid & 31;
    const int warp = tid >> 5;
    const int h    = blockIdx.x;
    const int b    = blockIdx.y;

    // ---------------- Phase 0: async copy of fragment-packed W ----------------
    {
        const size_t gsrc = __cvta_generic_to_global(g_AF) + (size_t)tid * 16;
        const uint32_t dst = sb + SMEM_AF + tid * 16;
        #pragma unroll
        for (int i = 0; i < 16; ++i) {
            asm volatile("cp.async.ca.shared.global [%0], [%1], 16;"
                         :: "r"(dst + i * 512 * 16), "l"(gsrc + (size_t)i * 512 * 16)
                         : "memory");
        }
        asm volatile("cp.async.commit_group;" ::: "memory");
    }

    // ---------------- Phase 1: depthwise -> Ys ----------------
    {
        const unsigned FULL = 0xFFFFFFFFu;
        #pragma unroll
        for (int i = 0; i < 8; ++i) {
            const int c = warp * 8 + i;
            const float r0 = rowk[c * 3 + 0], r1 = rowk[c * 3 + 1], r2 = rowk[c * 3 + 2];
            const float ck0 = colk[c * 3 + 0], ck1 = colk[c * 3 + 1], ck2 = colk[c * 3 + 2];
            const float* xc = x + ((size_t)(b * C_ + c) * H_) * W_;

            float y0 = 0.f, y1 = 0.f, y2 = 0.f, y3 = 0.f;
            #pragma unroll
            for (int dr = 0; dr < 3; ++dr) {
                const int row = h - 1 + dr;
                float4 v = make_float4(0.f, 0.f, 0.f, 0.f);
                if (row >= 0 && row < H_)
                    v = *(const float4*)(xc + (size_t)row * W_ + lane * 4);
                float left  = __shfl_up_sync(FULL, v.w, 1);
                float right = __shfl_down_sync(FULL, v.x, 1);
                if (lane == 0)  left = 0.f;
                if (lane == 31) right = 0.f;
                const float kc = (dr == 0) ? ck0 : (dr == 1) ? ck1 : ck2;
                y0 += kc * (r0 * left + r1 * v.x + r2 * v.y);
                y1 += kc * (r0 * v.x  + r1 * v.y + r2 * v.z);
                y2 += kc * (r0 * v.y  + r1 * v.z + r2 * v.w);
                y3 += kc * (r0 * v.z  + r1 * v.w + r2 * right);
            }
            uint4 ty;
            ty.x = f2tf32(y0); ty.y = f2tf32(y1); ty.z = f2tf32(y2); ty.w = f2tf32(y3);
            *(uint4*)(smem + SMEM_Y + ((size_t)c * YS_STRIDE + lane * 4) * 4) = ty;
        }
    }

    asm volatile("cp.async.wait_group 0;" ::: "memory");
    __syncthreads();

    // ---------------- Phase 2: GEMM (no interior barriers) ----------------
    const int wm = warp >> 2;   // 0..3 -> M offset wm*64 (mtiles wm*4 .. wm*4+3)
    const int wn = warp & 3;    // 0..3 -> N offset wn*32

    float acc[4][4][4] = {};

    // per-lane base addresses
    const uint32_t afBase = sb + SMEM_AF + ((wm * 4) * 32 + lane) * 16;  // + kstep*16*32*16 + mt*32*16
    const uint32_t ysBase = sb + SMEM_Y + ((lane & 3) * YS_STRIDE + wn * 32 + (lane >> 2)) * 4;

    #pragma unroll
    for (int k = 0; k < 16; ++k) {
        uint32_t a[4][4];
        uint32_t bf[4][2];
        #pragma unroll
        for (int mt = 0; mt < 4; ++mt) {
            const uint32_t addr = afBase + (uint32_t)(k * 16 * 32 * 16 + mt * 32 * 16);
            asm volatile("ld.shared.v4.b32 {%0,%1,%2,%3}, [%4];"
                         : "=r"(a[mt][0]), "=r"(a[mt][1]), "=r"(a[mt][2]), "=r"(a[mt][3])
                         : "r"(addr));
        }
        #pragma unroll
        for (int nt = 0; nt < 4; ++nt) {
            const uint32_t addr = ysBase + (uint32_t)((k * 8 * YS_STRIDE + nt * 8) * 4);
            asm volatile("ld.shared.b32 %0, [%1];" : "=r"(bf[nt][0]) : "r"(addr));
            asm volatile("ld.shared.b32 %0, [%1];" : "=r"(bf[nt][1])
                         : "r"(addr + 4u * YS_STRIDE * 4u));
        }
        #pragma unroll
        for (int mt = 0; mt < 4; ++mt)
            #pragma unroll
            for (int nt = 0; nt < 4; ++nt)
                mma_tf32(acc[mt][nt], a[mt], bf[nt]);
    }

    // ---------------- Epilogue ----------------
    float* ob = out + ((size_t)b * OUT_) * HW_ + (size_t)h * W_;
    #pragma unroll
    for (int mt = 0; mt < 4; ++mt) {
        int o0 = wm * 64 + mt * 16 + (lane >> 2);
        #pragma unroll
        for (int nt = 0; nt < 4; ++nt) {
            int p = wn * 32 + nt * 8 + (lane & 3) * 2;
            *(float2*)(ob + (size_t)o0 * HW_ + p) =
                make_float2(acc[mt][nt][0], acc[mt][nt][1]);
            *(float2*)(ob + (size_t)(o0 + 8) * HW_ + p) =
                make_float2(acc[mt][nt][2], acc[mt][nt][3]);
        }
    }
}

// ---------------------------------------------------------------------------
extern "C" void kernel_launch(void* const* d_in, const int* in_sizes, int n_in,
                              void* d_out, int out_size)
{
    (void)in_sizes; (void)n_in; (void)out_size;
    const float* x    = (const float*)d_in[0];
    const float* colk = (const float*)d_in[1];
    const float* rowk = (const float*)d_in[2];
    const float* pw   = (const float*)d_in[3];
    float* out = (float*)d_out;

    prep_kernel<<<64, 512>>>(pw);
    cudaFuncSetAttribute(fused_kernel, cudaFuncAttributeMaxDynamicSharedMemorySize, SMEM_TOT);
    fused_kernel<<<dim3(H_, B_), 512, SMEM_TOT>>>(x, colk, rowk, out);
}